// round 16
// baseline (speedup 1.0000x reference)
#include <cuda_runtime.h>
#include <math.h>

// ---------------------------------------------------------------------------
// NISQ classifier via Pauli-transfer-matrix simulation. R14 structure
// (sparse A0 in k1 + feats, masked B0, pruned A2, 9-tile B2 -> we, final dot)
// with Programmatic Dependent Launch chaining all 7 kernels.
// Qubit -> slot: q: 0 1 2 3 4 5 6 7 8 9 / slot: 0 2 3 4 5 1 6 7 8 9
// ---------------------------------------------------------------------------

#define NSTATE (1 << 20)
__device__ float g_c[NSTATE];                       // PTM state vector (4 MB)
__device__ __align__(16) float g_feats[2048 * 20];  // per-row Pauli features
__device__ float g_we[20];                          // w[k] * exps[k]

// S9 = {0,1,3,4,12,16,48,64,192}: 256-bit membership mask over bits4-11.
__device__ __constant__ unsigned long long PRMASK[4] =
    {0x000100000001101BULL, 1ULL, 0ULL, 1ULL};
__device__ __constant__ int TILE9[9] = {0, 1, 3, 4, 12, 16, 48, 64, 192};

// Observable table (R12-verified): k=0..9 X-part, k=10..19 Z-part.
__device__ __constant__ short OBS_T[20] =
    {0, 0, 0, 0, 0, 64, 16, 4, 1, 0,   0, 0, 0, 0, 0, 192, 48, 12, 3, 0};
__device__ __constant__ short OBS_U[20] =
    {1024, 256, 64, 16, 4, 0, 0, 0, 0, 1,   3072, 768, 192, 48, 12, 0, 0, 0, 0, 3};
__device__ __constant__ char OBS_W[20] =
    {18, 16, 14, 12, 10, 8, 6, 4, 2, 0,   19, 17, 15, 13, 11, 9, 7, 5, 3, 1};

// ---- PDL primitives (sm_90+; no-ops guarded) ----
__device__ __forceinline__ void pdl_trigger() {
#if __CUDA_ARCH__ >= 900
    asm volatile("griddepcontrol.launch_dependents;" ::: "memory");
#endif
}
__device__ __forceinline__ void pdl_wait() {
#if __CUDA_ARCH__ >= 900
    asm volatile("griddepcontrol.wait;" ::: "memory");
#endif
}

// Bank swizzle (R4-verified conflict-free for all pass patterns).
__device__ __host__ constexpr unsigned SWf(unsigned u) {
    return ((((u >> 5) ^ (u >> 7)) & 1u))
         | ((((u >> 6)) & 1u) << 1)
         | ((((u >> 5) ^ (u >> 6)) & 1u) << 2)
         | ((((u >> 6) ^ (u >> 7)) & 1u) << 3)
         | ((((u >> 8)) & 1u) << 4);
}

// Build fused single-qubit PTM op: M = phase*amp*depol1*Rot (4x4, row I = e0)
__device__ __forceinline__ void build_M(float phi, float th, float om, float* M) {
    float cphi = cosf(phi), sphi = sinf(phi);
    float cth  = cosf(th),  sth  = sinf(th);
    float com  = cosf(om),  som  = sinf(om);
    float A[9]  = {com, -som, 0.f,  som, com, 0.f,  0.f, 0.f, 1.f};
    float Bm[9] = {cth, 0.f, sth,   0.f, 1.f, 0.f,  -sth, 0.f, cth};
    float C[9]  = {cphi, -sphi, 0.f, sphi, cphi, 0.f, 0.f, 0.f, 1.f};
    float AB[9], R[9];
#pragma unroll
    for (int i = 0; i < 3; i++)
#pragma unroll
        for (int j = 0; j < 3; j++) {
            float s = 0.f;
#pragma unroll
            for (int k = 0; k < 3; k++) s += A[i*3+k] * Bm[k*3+j];
            AB[i*3+j] = s;
        }
#pragma unroll
    for (int i = 0; i < 3; i++)
#pragma unroll
        for (int j = 0; j < 3; j++) {
            float s = 0.f;
#pragma unroll
            for (int k = 0; k < 3; k++) s += AB[i*3+k] * C[k*3+j];
            R[i*3+j] = s;
        }
    const float gamma = -expm1f(-1e-7f / 0.05f);
    const float gph   = -expm1f(-1e-7f / 0.07f);
    const float c1    = 1.0f - 4.0f * 0.001f / 3.0f;
    float sq = sqrtf((1.f - gamma) * (1.f - gph));
    float a1 = sq * c1, z1 = (1.f - gamma) * c1, g1 = gamma;
    M[0]  = 1.f; M[1]  = 0.f;       M[2]  = 0.f;       M[3]  = 0.f;
    M[4]  = 0.f; M[5]  = a1 * R[0]; M[6]  = a1 * R[1]; M[7]  = a1 * R[2];
    M[8]  = 0.f; M[9]  = a1 * R[3]; M[10] = a1 * R[4]; M[11] = a1 * R[5];
    M[12] = g1;  M[13] = z1 * R[6]; M[14] = z1 * R[7]; M[15] = z1 * R[8];
}

// Fused pass (R4, best-measured): optional single ops, CNOT signed
// permutation, per-wire 2-qubit noise. One 16-elem group per thread (256 thr).
template<int PC, int PT, bool HASMT, bool HASMC>
__device__ __forceinline__ void pass(float* t,
                                     const float* __restrict__ MT,
                                     const float* __restrict__ MC,
                                     float aN, float zN, float gN) {
    constexpr int sc = 2 * PC, st = 2 * PT;
    constexpr int plo  = (sc < st) ? sc : st;
    constexpr int phi_ = (sc < st) ? st : sc;
    constexpr int midw = phi_ - plo - 2;
    unsigned g    = threadIdx.x;
    unsigned lo   = g & ((1u << plo) - 1u);
    unsigned rest = g >> plo;
    unsigned mid  = rest & ((1u << midw) - 1u);
    unsigned hi   = rest >> midw;
    unsigned base = lo | (mid << (plo + 2)) | (hi << (phi_ + 2));
    unsigned pb   = base ^ SWf(base);

    float v[16];
#pragma unroll
    for (int dc = 0; dc < 4; dc++)
#pragma unroll
        for (int dt = 0; dt < 4; dt++) {
            unsigned off = ((unsigned)dc << sc) | ((unsigned)dt << st);
            v[dc * 4 + dt] = t[pb ^ off ^ SWf(off)];
        }

    if (HASMT) {
#pragma unroll
        for (int dc = 0; dc < 4; dc++) {
            float v0 = v[dc*4+0], v1 = v[dc*4+1], v2 = v[dc*4+2], v3 = v[dc*4+3];
            v[dc*4+1] = MT[5]  * v1 + MT[6]  * v2 + MT[7]  * v3;
            v[dc*4+2] = MT[9]  * v1 + MT[10] * v2 + MT[11] * v3;
            v[dc*4+3] = MT[12] * v0 + MT[13] * v1 + MT[14] * v2 + MT[15] * v3;
        }
    }
    if (HASMC) {
#pragma unroll
        for (int dt = 0; dt < 4; dt++) {
            float v0 = v[0+dt], v1 = v[4+dt], v2 = v[8+dt], v3 = v[12+dt];
            v[4 + dt]  = MC[5]  * v1 + MC[6]  * v2 + MC[7]  * v3;
            v[8 + dt]  = MC[9]  * v1 + MC[10] * v2 + MC[11] * v3;
            v[12 + dt] = MC[12] * v0 + MC[13] * v1 + MC[14] * v2 + MC[15] * v3;
        }
    }

    const int tbl[16] = {0, 1, 14, 15, 5, 4, 11, 10, 9, 8, 7, 6, 12, 13, 2, 3};
    float w_[16];
#pragma unroll
    for (int i = 0; i < 16; i++) w_[i] = v[tbl[i]];
    w_[7]  = -w_[7];
    w_[10] = -w_[10];
#pragma unroll
    for (int dt = 0; dt < 4; dt++) {
        float u0 = w_[0+dt], u1 = w_[4+dt], u2 = w_[8+dt], u3 = w_[12+dt];
        w_[4 + dt]  = aN * u1;
        w_[8 + dt]  = aN * u2;
        w_[12 + dt] = gN * u0 + zN * u3;
    }
#pragma unroll
    for (int dc = 0; dc < 4; dc++) {
        float u0 = w_[dc*4+0], u1 = w_[dc*4+1], u2 = w_[dc*4+2], u3 = w_[dc*4+3];
        w_[dc*4+1] = aN * u1;
        w_[dc*4+2] = aN * u2;
        w_[dc*4+3] = gN * u0 + zN * u3;
    }
#pragma unroll
    for (int dc = 0; dc < 4; dc++)
#pragma unroll
        for (int dt = 0; dt < 4; dt++) {
            unsigned off = ((unsigned)dc << sc) | ((unsigned)dt << st);
            t[pb ^ off ^ SWf(off)] = w_[dc * 4 + dt];
        }
}

template<int KIND>
__device__ __forceinline__ unsigned gidx(unsigned u, unsigned tile) {
    if (KIND == 0) return u | (tile << 12);
    else           return (u & 15u) | (tile << 4) | ((u >> 4) << 12);
}

// One tile through a stage (R4 body, 256 threads).
// MASKLOAD (KIND 1 only): load only elements whose bits12-19 digits are I/Z.
template<int KIND, bool INIT, bool PRUNE, bool STORE, bool MASKLOAD>
__device__ __forceinline__ void stage_body(const float* __restrict__ wts,
                                           int layer, unsigned blk,
                                           float* t, float sM[10][16]) {
    unsigned tid = threadIdx.x;
    if (INIT) {
        for (unsigned u = tid; u < 4096; u += 256) {
            unsigned p = gidx<KIND>(u, blk);
            t[u ^ SWf(u)] = ((((p >> 1) ^ p) & 0x55555u) == 0u) ? 1.0f : 0.0f;
        }
    } else {
#pragma unroll
        for (int i = 0; i < 4; i++) {
            unsigned u = (tid + i * 256u) * 4u;
            float4 r;
            if (MASKLOAD) {
                unsigned d = (u >> 4) & 0xFFu;   // constant across the float4
                if ((((d >> 1) ^ d) & 0x55u) == 0u)
                    r = *(const float4*)&g_c[gidx<KIND>(u, blk)];
                else
                    r = make_float4(0.f, 0.f, 0.f, 0.f);
            } else {
                r = *(const float4*)&g_c[gidx<KIND>(u, blk)];
            }
            unsigned sw = SWf(u);
            t[(u + 0) ^ sw] = r.x;
            t[(u + 1) ^ sw] = r.y;
            t[(u + 2) ^ sw] = r.z;
            t[(u + 3) ^ sw] = r.w;
        }
    }
    if (tid < 10) {
        const float* a = wts + (layer * 10 + (int)tid) * 3;
        build_M(a[0], a[1], a[2], sM[tid]);
    }
    __syncthreads();

    const float gamma = -expm1f(-1e-7f / 0.05f);
    const float gph   = -expm1f(-1e-7f / 0.07f);
    const float c2    = 1.0f - 4.0f * 0.01f / 3.0f;
    const float aN = sqrtf((1.f - gamma) * (1.f - gph)) * c2;
    const float zN = (1.f - gamma) * c2;
    const float gN = gamma;

    if (KIND == 0) {
        pass<0, 2, true, true >(t, sM[1], sM[0], aN, zN, gN); __syncthreads();
        pass<2, 3, true, false>(t, sM[2], 0,     aN, zN, gN); __syncthreads();
        pass<3, 4, true, false>(t, sM[3], 0,     aN, zN, gN); __syncthreads();
        pass<4, 5, true, false>(t, sM[4], 0,     aN, zN, gN); __syncthreads();
        pass<5, 1, true, false>(t, sM[5], 0,     aN, zN, gN); __syncthreads();
    } else {
        pass<1, 2, true, false>(t, sM[6], 0, aN, zN, gN); __syncthreads();
        pass<2, 3, true, false>(t, sM[7], 0, aN, zN, gN); __syncthreads();
        pass<3, 4, true, false>(t, sM[8], 0, aN, zN, gN); __syncthreads();
        pass<4, 5, true, false>(t, sM[9], 0, aN, zN, gN); __syncthreads();
        pass<5, 0, false,false>(t, 0,     0, aN, zN, gN); __syncthreads();
    }

    if (STORE) {
#pragma unroll
        for (int i = 0; i < 4; i++) {
            unsigned u = (tid + i * 256u) * 4u;
            if (PRUNE) {
                unsigned vsel = (u >> 4) & 0xFFu;
                if (!((PRMASK[vsel >> 6] >> (vsel & 63u)) & 1ull)) continue;
            }
            unsigned sw = SWf(u);
            float4 r;
            r.x = t[(u + 0) ^ sw];
            r.y = t[(u + 1) ^ sw];
            r.z = t[(u + 2) ^ sw];
            r.w = t[(u + 3) ^ sw];
            *(float4*)&g_c[gidx<KIND>(u, blk)] = r;
        }
    }
}

// ---------------------------------------------------------------------------
// feats: warp-per-row, register-resident, no smem/syncs (R12-verified).
// ---------------------------------------------------------------------------
__device__ __forceinline__ float dot4(const float* a, const float* b) {
    return a[0]*b[0] + a[1]*b[1] + a[2]*b[2] + a[3]*b[3];
}

__device__ void feats_body(const float* __restrict__ x,
                           const float* __restrict__ bvec, int fblk) {
    int lane = threadIdx.x & 31;
    int row  = fblk * 8 + (threadIdx.x >> 5);
    const float4* xr = (const float4*)(x + row * 1024);
    const float4* br = (const float4*)bvec;

    float e[8][4];
#pragma unroll
    for (int t = 0; t < 8; t++) {
        float4 xv = xr[lane + 32 * t];
        float4 bb = br[lane + 32 * t];
        e[t][0] = xv.x + bb.x; e[t][1] = xv.y + bb.y;
        e[t][2] = xv.z + bb.z; e[t][3] = xv.w + bb.w;
    }

    float fA[10], fZ[10];
#pragma unroll
    for (int j = 0; j < 10; j++) { fA[j] = 0.f; fZ[j] = 0.f; }
    float Stot = 0.f;

#pragma unroll
    for (int t = 0; t < 8; t++) {
        float s0 = e[t][0]*e[t][0], s1 = e[t][1]*e[t][1];
        float s2 = e[t][2]*e[t][2], s3 = e[t][3]*e[t][3];
        float St = (s0 + s1) + (s2 + s3);
        Stot += St;
        fZ[0] += (s0 - s1) + (s2 - s3);
        fZ[1] += (s0 + s1) - (s2 + s3);
        fZ[7] += (t & 1) ? -St : St;
        fZ[8] += (t & 2) ? -St : St;
        fZ[9] += (t & 4) ? -St : St;
        fA[0] += 2.f * (e[t][0]*e[t][1] + e[t][2]*e[t][3]);
        fA[1] += 2.f * (e[t][0]*e[t][2] + e[t][1]*e[t][3]);
    }
#pragma unroll
    for (int j = 2; j <= 6; j++)
        fZ[j] = ((lane >> (j - 2)) & 1) ? -Stot : Stot;

    fA[7] = 2.f * (dot4(e[0],e[1]) + dot4(e[2],e[3]) + dot4(e[4],e[5]) + dot4(e[6],e[7]));
    fA[8] = 2.f * (dot4(e[0],e[2]) + dot4(e[1],e[3]) + dot4(e[4],e[6]) + dot4(e[5],e[7]));
    fA[9] = 2.f * (dot4(e[0],e[4]) + dot4(e[1],e[5]) + dot4(e[2],e[6]) + dot4(e[3],e[7]));

#pragma unroll
    for (int j = 2; j <= 6; j++) {
        int b = 1 << (j - 2);
        float acc = 0.f;
#pragma unroll
        for (int t = 0; t < 8; t++)
#pragma unroll
            for (int k = 0; k < 4; k++) {
                float nb = __shfl_xor_sync(0xFFFFFFFFu, e[t][k], b);
                acc += e[t][k] * nb;
            }
        fA[j] = acc;
    }

#pragma unroll
    for (int j = 0; j < 10; j++) {
#pragma unroll
        for (int off = 16; off > 0; off >>= 1) {
            fA[j] += __shfl_down_sync(0xFFFFFFFFu, fA[j], off);
            fZ[j] += __shfl_down_sync(0xFFFFFFFFu, fZ[j], off);
        }
    }
    if (lane == 0) {
#pragma unroll
        for (int j = 0; j < 10; j++) {
            g_feats[row * 20 + j]      = fA[j];
            g_feats[row * 20 + 10 + j] = fZ[j];
        }
    }
}

// ---------------------------------------------------------------------------
// K1: blocks 0-15 = sim stage A0 (16 nonzero tiles); blocks 16-271 = feats.
// ---------------------------------------------------------------------------
__global__ __launch_bounds__(256) void k1_kernel(const float* __restrict__ wts,
                                                 const float* __restrict__ x,
                                                 const float* __restrict__ bvec) {
    pdl_trigger();   // let B0 begin launching under us
    __shared__ float t[4096];
    __shared__ float sM[10][16];
    if (blockIdx.x < 16) {
        unsigned b = blockIdx.x;
        unsigned tile = 0;
        if (b & 1) tile |= 3u;
        if (b & 2) tile |= 3u << 2;
        if (b & 4) tile |= 3u << 4;
        if (b & 8) tile |= 3u << 6;
        stage_body<0, true, false, true, false>(wts, 0, tile, t, sM);
    } else {
        feats_body(x, bvec, (int)blockIdx.x - 16);
    }
}

// Generic sim stage kernel. REMAP: 9 observable tiles; emits g_we, no stores.
template<int KIND, bool PRUNE, bool REMAP, bool MASKLOAD>
__global__ __launch_bounds__(256) void sim_kernel(const float* __restrict__ wts,
                                                  const float* __restrict__ w,
                                                  int layer) {
    pdl_trigger();   // successor may begin launching
    pdl_wait();      // predecessor's g_c writes visible after this
    __shared__ float t[4096];
    __shared__ float sM[10][16];
    unsigned blk = REMAP ? (unsigned)TILE9[blockIdx.x] : blockIdx.x;
    stage_body<KIND, false, PRUNE, !REMAP, MASKLOAD>(wts, layer, blk, t, sM);
    if (REMAP) {
        unsigned tid = threadIdx.x;
        if (tid < 20 && (unsigned)OBS_T[tid] == blk) {
            unsigned u = (unsigned)OBS_U[tid];
            float v = t[u ^ SWf(u)];
            float coef = w[(int)OBS_W[tid]] * (tid < 10 ? 1.0f : 0.96f);
            g_we[tid] = coef * v;
        }
    }
}

// Final: logit[row] = dot(feats[row], we); sigmoid.
__global__ __launch_bounds__(256) void final_kernel(float* __restrict__ out) {
    pdl_wait();      // B2 complete (transitively: whole chain complete)
    int row = blockIdx.x * 256 + threadIdx.x;
    const float4* f = (const float4*)(g_feats + row * 20);
    float acc = 0.f;
#pragma unroll
    for (int i = 0; i < 5; i++) {
        float4 v = f[i];
        acc += v.x * g_we[i*4+0] + v.y * g_we[i*4+1]
             + v.z * g_we[i*4+2] + v.w * g_we[i*4+3];
    }
    out[row] = 1.f / (1.f + expf(-acc));
}

// ---------------------------------------------------------------------------
extern "C" void kernel_launch(void* const* d_in, const int* in_sizes, int n_in,
                              void* d_out, int out_size) {
    const float* x = nullptr;
    const float* bv = nullptr;
    const float* w = nullptr;
    const float* cw = nullptr;
    for (int i = 0; i < n_in; i++) {
        switch (in_sizes[i]) {
            case 2048 * 1024: x = (const float*)d_in[i]; break;
            case 1024:        bv = (const float*)d_in[i]; break;
            case 20:          w = (const float*)d_in[i]; break;
            case 90:          cw = (const float*)d_in[i]; break;
            default: break;  // P_tensor unused
        }
    }

    cudaLaunchAttribute pdl[1];
    pdl[0].id = cudaLaunchAttributeProgrammaticStreamSerialization;
    pdl[0].val.programmaticStreamSerializationAllowed = 1;

    cudaLaunchConfig_t cfg = {};
    cfg.blockDim = dim3(256, 1, 1);
    cfg.stream = 0;

    // k1: first kernel, no PDL attribute needed.
    cfg.gridDim = dim3(272, 1, 1);
    cfg.attrs = nullptr; cfg.numAttrs = 0;
    cudaLaunchKernelEx(&cfg, k1_kernel, cw, x, bv);

    cfg.attrs = pdl; cfg.numAttrs = 1;
    cfg.gridDim = dim3(256, 1, 1);
    cudaLaunchKernelEx(&cfg, sim_kernel<1, false, false, true >, cw, w, 0); // B0
    cudaLaunchKernelEx(&cfg, sim_kernel<0, false, false, false>, cw, w, 1); // A1
    cudaLaunchKernelEx(&cfg, sim_kernel<1, false, false, false>, cw, w, 1); // B1
    cudaLaunchKernelEx(&cfg, sim_kernel<0, true,  false, false>, cw, w, 2); // A2 (PRUNE)
    cfg.gridDim = dim3(9, 1, 1);
    cudaLaunchKernelEx(&cfg, sim_kernel<1, false, true,  false>, cw, w, 2); // B2 -> g_we
    cfg.gridDim = dim3(8, 1, 1);
    float* outp = (float*)d_out;
    cudaLaunchKernelEx(&cfg, final_kernel, outp);
}

// round 17
// speedup vs baseline: 1.0197x; 1.0197x over previous
#include <cuda_runtime.h>
#include <math.h>

// ---------------------------------------------------------------------------
// NISQ classifier via Pauli-transfer-matrix simulation. R14 structure
// (sparse A0, masked B0, pruned A2, 9-tile B2 -> we, final dot) with the
// feats work (DRAM-bound, sim-independent) spread as extra blocks across
// k1/B0/A1/B1 to hide under the latency-bound sim stages.
// Qubit -> slot: q: 0 1 2 3 4 5 6 7 8 9 / slot: 0 2 3 4 5 1 6 7 8 9
// ---------------------------------------------------------------------------

#define NSTATE (1 << 20)
__device__ float g_c[NSTATE];                       // PTM state vector (4 MB)
__device__ __align__(16) float g_feats[2048 * 20];  // per-row Pauli features
__device__ float g_we[20];                          // w[k] * exps[k]

// S9 = {0,1,3,4,12,16,48,64,192}: 256-bit membership mask over bits4-11.
__device__ __constant__ unsigned long long PRMASK[4] =
    {0x000100000001101BULL, 1ULL, 0ULL, 1ULL};
__device__ __constant__ int TILE9[9] = {0, 1, 3, 4, 12, 16, 48, 64, 192};

// Observable table (R12-verified): k=0..9 X-part, k=10..19 Z-part.
__device__ __constant__ short OBS_T[20] =
    {0, 0, 0, 0, 0, 64, 16, 4, 1, 0,   0, 0, 0, 0, 0, 192, 48, 12, 3, 0};
__device__ __constant__ short OBS_U[20] =
    {1024, 256, 64, 16, 4, 0, 0, 0, 0, 1,   3072, 768, 192, 48, 12, 0, 0, 0, 0, 3};
__device__ __constant__ char OBS_W[20] =
    {18, 16, 14, 12, 10, 8, 6, 4, 2, 0,   19, 17, 15, 13, 11, 9, 7, 5, 3, 1};

// Bank swizzle (R4-verified conflict-free for all pass patterns).
__device__ __host__ constexpr unsigned SWf(unsigned u) {
    return ((((u >> 5) ^ (u >> 7)) & 1u))
         | ((((u >> 6)) & 1u) << 1)
         | ((((u >> 5) ^ (u >> 6)) & 1u) << 2)
         | ((((u >> 6) ^ (u >> 7)) & 1u) << 3)
         | ((((u >> 8)) & 1u) << 4);
}

// Build fused single-qubit PTM op: M = phase*amp*depol1*Rot (4x4, row I = e0)
__device__ __forceinline__ void build_M(float phi, float th, float om, float* M) {
    float cphi = cosf(phi), sphi = sinf(phi);
    float cth  = cosf(th),  sth  = sinf(th);
    float com  = cosf(om),  som  = sinf(om);
    float A[9]  = {com, -som, 0.f,  som, com, 0.f,  0.f, 0.f, 1.f};
    float Bm[9] = {cth, 0.f, sth,   0.f, 1.f, 0.f,  -sth, 0.f, cth};
    float C[9]  = {cphi, -sphi, 0.f, sphi, cphi, 0.f, 0.f, 0.f, 1.f};
    float AB[9], R[9];
#pragma unroll
    for (int i = 0; i < 3; i++)
#pragma unroll
        for (int j = 0; j < 3; j++) {
            float s = 0.f;
#pragma unroll
            for (int k = 0; k < 3; k++) s += A[i*3+k] * Bm[k*3+j];
            AB[i*3+j] = s;
        }
#pragma unroll
    for (int i = 0; i < 3; i++)
#pragma unroll
        for (int j = 0; j < 3; j++) {
            float s = 0.f;
#pragma unroll
            for (int k = 0; k < 3; k++) s += AB[i*3+k] * C[k*3+j];
            R[i*3+j] = s;
        }
    const float gamma = -expm1f(-1e-7f / 0.05f);
    const float gph   = -expm1f(-1e-7f / 0.07f);
    const float c1    = 1.0f - 4.0f * 0.001f / 3.0f;
    float sq = sqrtf((1.f - gamma) * (1.f - gph));
    float a1 = sq * c1, z1 = (1.f - gamma) * c1, g1 = gamma;
    M[0]  = 1.f; M[1]  = 0.f;       M[2]  = 0.f;       M[3]  = 0.f;
    M[4]  = 0.f; M[5]  = a1 * R[0]; M[6]  = a1 * R[1]; M[7]  = a1 * R[2];
    M[8]  = 0.f; M[9]  = a1 * R[3]; M[10] = a1 * R[4]; M[11] = a1 * R[5];
    M[12] = g1;  M[13] = z1 * R[6]; M[14] = z1 * R[7]; M[15] = z1 * R[8];
}

// Fused pass (R4, best-measured): optional single ops, CNOT signed
// permutation, per-wire 2-qubit noise. One 16-elem group per thread (256 thr).
template<int PC, int PT, bool HASMT, bool HASMC>
__device__ __forceinline__ void pass(float* t,
                                     const float* __restrict__ MT,
                                     const float* __restrict__ MC,
                                     float aN, float zN, float gN) {
    constexpr int sc = 2 * PC, st = 2 * PT;
    constexpr int plo  = (sc < st) ? sc : st;
    constexpr int phi_ = (sc < st) ? st : sc;
    constexpr int midw = phi_ - plo - 2;
    unsigned g    = threadIdx.x;
    unsigned lo   = g & ((1u << plo) - 1u);
    unsigned rest = g >> plo;
    unsigned mid  = rest & ((1u << midw) - 1u);
    unsigned hi   = rest >> midw;
    unsigned base = lo | (mid << (plo + 2)) | (hi << (phi_ + 2));
    unsigned pb   = base ^ SWf(base);

    float v[16];
#pragma unroll
    for (int dc = 0; dc < 4; dc++)
#pragma unroll
        for (int dt = 0; dt < 4; dt++) {
            unsigned off = ((unsigned)dc << sc) | ((unsigned)dt << st);
            v[dc * 4 + dt] = t[pb ^ off ^ SWf(off)];
        }

    if (HASMT) {
#pragma unroll
        for (int dc = 0; dc < 4; dc++) {
            float v0 = v[dc*4+0], v1 = v[dc*4+1], v2 = v[dc*4+2], v3 = v[dc*4+3];
            v[dc*4+1] = MT[5]  * v1 + MT[6]  * v2 + MT[7]  * v3;
            v[dc*4+2] = MT[9]  * v1 + MT[10] * v2 + MT[11] * v3;
            v[dc*4+3] = MT[12] * v0 + MT[13] * v1 + MT[14] * v2 + MT[15] * v3;
        }
    }
    if (HASMC) {
#pragma unroll
        for (int dt = 0; dt < 4; dt++) {
            float v0 = v[0+dt], v1 = v[4+dt], v2 = v[8+dt], v3 = v[12+dt];
            v[4 + dt]  = MC[5]  * v1 + MC[6]  * v2 + MC[7]  * v3;
            v[8 + dt]  = MC[9]  * v1 + MC[10] * v2 + MC[11] * v3;
            v[12 + dt] = MC[12] * v0 + MC[13] * v1 + MC[14] * v2 + MC[15] * v3;
        }
    }

    const int tbl[16] = {0, 1, 14, 15, 5, 4, 11, 10, 9, 8, 7, 6, 12, 13, 2, 3};
    float w_[16];
#pragma unroll
    for (int i = 0; i < 16; i++) w_[i] = v[tbl[i]];
    w_[7]  = -w_[7];
    w_[10] = -w_[10];
#pragma unroll
    for (int dt = 0; dt < 4; dt++) {
        float u0 = w_[0+dt], u1 = w_[4+dt], u2 = w_[8+dt], u3 = w_[12+dt];
        w_[4 + dt]  = aN * u1;
        w_[8 + dt]  = aN * u2;
        w_[12 + dt] = gN * u0 + zN * u3;
    }
#pragma unroll
    for (int dc = 0; dc < 4; dc++) {
        float u0 = w_[dc*4+0], u1 = w_[dc*4+1], u2 = w_[dc*4+2], u3 = w_[dc*4+3];
        w_[dc*4+1] = aN * u1;
        w_[dc*4+2] = aN * u2;
        w_[dc*4+3] = gN * u0 + zN * u3;
    }
#pragma unroll
    for (int dc = 0; dc < 4; dc++)
#pragma unroll
        for (int dt = 0; dt < 4; dt++) {
            unsigned off = ((unsigned)dc << sc) | ((unsigned)dt << st);
            t[pb ^ off ^ SWf(off)] = w_[dc * 4 + dt];
        }
}

template<int KIND>
__device__ __forceinline__ unsigned gidx(unsigned u, unsigned tile) {
    if (KIND == 0) return u | (tile << 12);
    else           return (u & 15u) | (tile << 4) | ((u >> 4) << 12);
}

// One tile through a stage (R4 body, 256 threads).
// MASKLOAD (KIND 1 only): load only elements whose bits12-19 digits are I/Z.
template<int KIND, bool INIT, bool PRUNE, bool STORE, bool MASKLOAD>
__device__ __forceinline__ void stage_body(const float* __restrict__ wts,
                                           int layer, unsigned blk,
                                           float* t, float sM[10][16]) {
    unsigned tid = threadIdx.x;
    if (INIT) {
        for (unsigned u = tid; u < 4096; u += 256) {
            unsigned p = gidx<KIND>(u, blk);
            t[u ^ SWf(u)] = ((((p >> 1) ^ p) & 0x55555u) == 0u) ? 1.0f : 0.0f;
        }
    } else {
#pragma unroll
        for (int i = 0; i < 4; i++) {
            unsigned u = (tid + i * 256u) * 4u;
            float4 r;
            if (MASKLOAD) {
                unsigned d = (u >> 4) & 0xFFu;   // constant across the float4
                if ((((d >> 1) ^ d) & 0x55u) == 0u)
                    r = *(const float4*)&g_c[gidx<KIND>(u, blk)];
                else
                    r = make_float4(0.f, 0.f, 0.f, 0.f);
            } else {
                r = *(const float4*)&g_c[gidx<KIND>(u, blk)];
            }
            unsigned sw = SWf(u);
            t[(u + 0) ^ sw] = r.x;
            t[(u + 1) ^ sw] = r.y;
            t[(u + 2) ^ sw] = r.z;
            t[(u + 3) ^ sw] = r.w;
        }
    }
    if (tid < 10) {
        const float* a = wts + (layer * 10 + (int)tid) * 3;
        build_M(a[0], a[1], a[2], sM[tid]);
    }
    __syncthreads();

    const float gamma = -expm1f(-1e-7f / 0.05f);
    const float gph   = -expm1f(-1e-7f / 0.07f);
    const float c2    = 1.0f - 4.0f * 0.01f / 3.0f;
    const float aN = sqrtf((1.f - gamma) * (1.f - gph)) * c2;
    const float zN = (1.f - gamma) * c2;
    const float gN = gamma;

    if (KIND == 0) {
        pass<0, 2, true, true >(t, sM[1], sM[0], aN, zN, gN); __syncthreads();
        pass<2, 3, true, false>(t, sM[2], 0,     aN, zN, gN); __syncthreads();
        pass<3, 4, true, false>(t, sM[3], 0,     aN, zN, gN); __syncthreads();
        pass<4, 5, true, false>(t, sM[4], 0,     aN, zN, gN); __syncthreads();
        pass<5, 1, true, false>(t, sM[5], 0,     aN, zN, gN); __syncthreads();
    } else {
        pass<1, 2, true, false>(t, sM[6], 0, aN, zN, gN); __syncthreads();
        pass<2, 3, true, false>(t, sM[7], 0, aN, zN, gN); __syncthreads();
        pass<3, 4, true, false>(t, sM[8], 0, aN, zN, gN); __syncthreads();
        pass<4, 5, true, false>(t, sM[9], 0, aN, zN, gN); __syncthreads();
        pass<5, 0, false,false>(t, 0,     0, aN, zN, gN); __syncthreads();
    }

    if (STORE) {
#pragma unroll
        for (int i = 0; i < 4; i++) {
            unsigned u = (tid + i * 256u) * 4u;
            if (PRUNE) {
                unsigned vsel = (u >> 4) & 0xFFu;
                if (!((PRMASK[vsel >> 6] >> (vsel & 63u)) & 1ull)) continue;
            }
            unsigned sw = SWf(u);
            float4 r;
            r.x = t[(u + 0) ^ sw];
            r.y = t[(u + 1) ^ sw];
            r.z = t[(u + 2) ^ sw];
            r.w = t[(u + 3) ^ sw];
            *(float4*)&g_c[gidx<KIND>(u, blk)] = r;
        }
    }
}

// ---------------------------------------------------------------------------
// feats: warp-per-row, register-resident, no smem/syncs (R12-verified).
// ---------------------------------------------------------------------------
__device__ __forceinline__ float dot4(const float* a, const float* b) {
    return a[0]*b[0] + a[1]*b[1] + a[2]*b[2] + a[3]*b[3];
}

__device__ void feats_body(const float* __restrict__ x,
                           const float* __restrict__ bvec, int fblk) {
    int lane = threadIdx.x & 31;
    int row  = fblk * 8 + (threadIdx.x >> 5);
    const float4* xr = (const float4*)(x + row * 1024);
    const float4* br = (const float4*)bvec;

    float e[8][4];
#pragma unroll
    for (int t = 0; t < 8; t++) {
        float4 xv = xr[lane + 32 * t];
        float4 bb = br[lane + 32 * t];
        e[t][0] = xv.x + bb.x; e[t][1] = xv.y + bb.y;
        e[t][2] = xv.z + bb.z; e[t][3] = xv.w + bb.w;
    }

    float fA[10], fZ[10];
#pragma unroll
    for (int j = 0; j < 10; j++) { fA[j] = 0.f; fZ[j] = 0.f; }
    float Stot = 0.f;

#pragma unroll
    for (int t = 0; t < 8; t++) {
        float s0 = e[t][0]*e[t][0], s1 = e[t][1]*e[t][1];
        float s2 = e[t][2]*e[t][2], s3 = e[t][3]*e[t][3];
        float St = (s0 + s1) + (s2 + s3);
        Stot += St;
        fZ[0] += (s0 - s1) + (s2 - s3);
        fZ[1] += (s0 + s1) - (s2 + s3);
        fZ[7] += (t & 1) ? -St : St;
        fZ[8] += (t & 2) ? -St : St;
        fZ[9] += (t & 4) ? -St : St;
        fA[0] += 2.f * (e[t][0]*e[t][1] + e[t][2]*e[t][3]);
        fA[1] += 2.f * (e[t][0]*e[t][2] + e[t][1]*e[t][3]);
    }
#pragma unroll
    for (int j = 2; j <= 6; j++)
        fZ[j] = ((lane >> (j - 2)) & 1) ? -Stot : Stot;

    fA[7] = 2.f * (dot4(e[0],e[1]) + dot4(e[2],e[3]) + dot4(e[4],e[5]) + dot4(e[6],e[7]));
    fA[8] = 2.f * (dot4(e[0],e[2]) + dot4(e[1],e[3]) + dot4(e[4],e[6]) + dot4(e[5],e[7]));
    fA[9] = 2.f * (dot4(e[0],e[4]) + dot4(e[1],e[5]) + dot4(e[2],e[6]) + dot4(e[3],e[7]));

#pragma unroll
    for (int j = 2; j <= 6; j++) {
        int b = 1 << (j - 2);
        float acc = 0.f;
#pragma unroll
        for (int t = 0; t < 8; t++)
#pragma unroll
            for (int k = 0; k < 4; k++) {
                float nb = __shfl_xor_sync(0xFFFFFFFFu, e[t][k], b);
                acc += e[t][k] * nb;
            }
        fA[j] = acc;
    }

#pragma unroll
    for (int j = 0; j < 10; j++) {
#pragma unroll
        for (int off = 16; off > 0; off >>= 1) {
            fA[j] += __shfl_down_sync(0xFFFFFFFFu, fA[j], off);
            fZ[j] += __shfl_down_sync(0xFFFFFFFFu, fZ[j], off);
        }
    }
    if (lane == 0) {
#pragma unroll
        for (int j = 0; j < 10; j++) {
            g_feats[row * 20 + j]      = fA[j];
            g_feats[row * 20 + 10 + j] = fZ[j];
        }
    }
}

// ---------------------------------------------------------------------------
// K1: blocks 0-15 = sim stage A0 (16 nonzero tiles); blocks 16-79 = feats.
// ---------------------------------------------------------------------------
__global__ __launch_bounds__(256) void k1_kernel(const float* __restrict__ wts,
                                                 const float* __restrict__ x,
                                                 const float* __restrict__ bvec) {
    __shared__ float t[4096];
    __shared__ float sM[10][16];
    if (blockIdx.x < 16) {
        unsigned b = blockIdx.x;
        unsigned tile = 0;
        if (b & 1) tile |= 3u;
        if (b & 2) tile |= 3u << 2;
        if (b & 4) tile |= 3u << 4;
        if (b & 8) tile |= 3u << 6;
        stage_body<0, true, false, true, false>(wts, 0, tile, t, sM);
    } else {
        feats_body(x, bvec, (int)blockIdx.x - 16);   // fblk 0..63
    }
}

// Generic sim stage kernel. Blocks >= 256 run feats (when FEATS).
// REMAP: 9 observable tiles; emits g_we, no stores.
template<int KIND, bool PRUNE, bool REMAP, bool MASKLOAD, bool FEATS>
__global__ __launch_bounds__(256) void sim_kernel(const float* __restrict__ wts,
                                                  const float* __restrict__ w,
                                                  int layer,
                                                  const float* __restrict__ x,
                                                  const float* __restrict__ bvec,
                                                  int fbase) {
    if (FEATS && blockIdx.x >= 256) {
        feats_body(x, bvec, fbase + (int)blockIdx.x - 256);
        return;
    }
    __shared__ float t[4096];
    __shared__ float sM[10][16];
    unsigned blk = REMAP ? (unsigned)TILE9[blockIdx.x] : blockIdx.x;
    stage_body<KIND, false, PRUNE, !REMAP, MASKLOAD>(wts, layer, blk, t, sM);
    if (REMAP) {
        unsigned tid = threadIdx.x;
        if (tid < 20 && (unsigned)OBS_T[tid] == blk) {
            unsigned u = (unsigned)OBS_U[tid];
            float v = t[u ^ SWf(u)];
            float coef = w[(int)OBS_W[tid]] * (tid < 10 ? 1.0f : 0.96f);
            g_we[tid] = coef * v;
        }
    }
}

// Final: logit[row] = dot(feats[row], we); sigmoid.
__global__ __launch_bounds__(256) void final_kernel(float* __restrict__ out) {
    int row = blockIdx.x * 256 + threadIdx.x;
    const float4* f = (const float4*)(g_feats + row * 20);
    float acc = 0.f;
#pragma unroll
    for (int i = 0; i < 5; i++) {
        float4 v = f[i];
        acc += v.x * g_we[i*4+0] + v.y * g_we[i*4+1]
             + v.z * g_we[i*4+2] + v.w * g_we[i*4+3];
    }
    out[row] = 1.f / (1.f + expf(-acc));
}

// ---------------------------------------------------------------------------
extern "C" void kernel_launch(void* const* d_in, const int* in_sizes, int n_in,
                              void* d_out, int out_size) {
    const float* x = nullptr;
    const float* bv = nullptr;
    const float* w = nullptr;
    const float* cw = nullptr;
    for (int i = 0; i < n_in; i++) {
        switch (in_sizes[i]) {
            case 2048 * 1024: x = (const float*)d_in[i]; break;
            case 1024:        bv = (const float*)d_in[i]; break;
            case 20:          w = (const float*)d_in[i]; break;
            case 90:          cw = (const float*)d_in[i]; break;
            default: break;  // P_tensor unused
        }
    }

    // Template args: <KIND, PRUNE, REMAP, MASKLOAD, FEATS>
    // feats rows split: k1 fblk 0-63, B0 64-127, A1 128-191, B1 192-255.
    k1_kernel<<<80, 256>>>(cw, x, bv);                                        // A0(16) + feats
    sim_kernel<1, false, false, true,  true ><<<320, 256>>>(cw, w, 0, x, bv, 64);  // B0 + feats
    sim_kernel<0, false, false, false, true ><<<320, 256>>>(cw, w, 1, x, bv, 128); // A1 + feats
    sim_kernel<1, false, false, false, true ><<<320, 256>>>(cw, w, 1, x, bv, 192); // B1 + feats
    sim_kernel<0, true,  false, false, false><<<256, 256>>>(cw, w, 2, x, bv, 0);   // A2 (PRUNE)
    sim_kernel<1, false, true,  false, false><<<9,   256>>>(cw, w, 2, x, bv, 0);   // B2 -> g_we
    final_kernel<<<8, 256>>>((float*)d_out);                                  // dot + sigmoid
}